// round 12
// baseline (speedup 1.0000x reference)
#include <cuda_runtime.h>

// DigitCaps dynamic routing, fully fused, one block per batch element.
// Round 3: 256 fat threads; WV and y both register-resident in the main loop
// (zero LDS in the hot path); RF-feasible (≈220 regs x 256 thr < 64K).

#define C_   32
#define HW_  144
#define Q_   8
#define O_   10
#define P_   16
#define NT   256      // 32 c-lanes x 8 hw-group warps; 18 hw per thread

// shared memory layout (floats)
#define OFF_WV   0                       // WV per-c rows: [c*84 + o*8 + q]
#define WV_ROW   84                      // 16B-aligned rows; 20*lane conflict-free per 8-phase
#define OFF_Y    2688                    // y: [c*82 + o*8 + q]
#define Y_ROW    82                      // 18*lane distinct per 16-phase (8B ops)
#define OFF_PART 5312                    // per-thread y partials [256][82]
#define PART_ROW 82
#define OFF_VS   (OFF_PART + NT*PART_ROW)    // 26304: vsum accumulator [160]
#define SMEM_FLOATS (OFF_VS + 160)           // 26464 floats = 105856 B

// ---- packed fp32x2 helpers (double = 64-bit carrier) ----
__device__ __forceinline__ double dfma2(double a, double b, double c) {
    double d; asm("fma.rn.f32x2 %0,%1,%2,%3;" : "=d"(d) : "d"(a), "d"(b), "d"(c)); return d;
}
__device__ __forceinline__ double dmul2(double a, double b) {
    double d; asm("mul.rn.f32x2 %0,%1,%2;" : "=d"(d) : "d"(a), "d"(b)); return d;
}
__device__ __forceinline__ double dadd2(double a, double b) {
    double d; asm("add.rn.f32x2 %0,%1,%2;" : "=d"(d) : "d"(a), "d"(b)); return d;
}
__device__ __forceinline__ double dpack(float lo, float hi) {
    double d; asm("mov.b64 %0,{%1,%2};" : "=d"(d) : "f"(lo), "f"(hi)); return d;
}
__device__ __forceinline__ float dhadd(double a) {
    float lo, hi; asm("mov.b64 {%0,%1},%2;" : "=f"(lo), "=f"(hi) : "d"(a)); return lo + hi;
}

__device__ __forceinline__ double s_part(const float* __restrict__ W, const float* sm,
                                         int cc, int o, int p, double acc)
{
    const double2* wp = reinterpret_cast<const double2*>(
        W + ((size_t)(cc * O_ + o) * P_ + p) * Q_);
    const double* yp = reinterpret_cast<const double*>(sm + OFF_Y + cc * Y_ROW + o * 8);
    const double2 wa = wp[0], wb = wp[1];
    acc = dfma2(wa.x, yp[0], acc); acc = dfma2(wa.y, yp[1], acc);
    acc = dfma2(wb.x, yp[2], acc); acc = dfma2(wb.y, yp[3], acc);
    return acc;
}

// s[o,p] = sum_{c,q} W[c,o,p,q]*y[c,o,q]  -> squash -> vsum/out. Single stage.
__device__ __forceinline__ void squash_update(float* sm, const float* __restrict__ W,
                                              bool accum_vs, float* __restrict__ outp, int t)
{
    if (t < 160) {
        const int o = t >> 4, p = t & 15;
        double a0 = 0.0, a1 = 0.0, a2 = 0.0, a3 = 0.0;
        #pragma unroll
        for (int ci = 0; ci < 8; ++ci) {
            a0 = s_part(W, sm, ci,      o, p, a0);
            a1 = s_part(W, sm, ci + 8,  o, p, a1);
            a2 = s_part(W, sm, ci + 16, o, p, a2);
            a3 = s_part(W, sm, ci + 24, o, p, a3);
        }
        const float s = dhadd(dadd2(dadd2(a0, a1), dadd2(a2, a3)));
        float sq = s * s;
        sq += __shfl_xor_sync(0xffffffffu, sq, 1);
        sq += __shfl_xor_sync(0xffffffffu, sq, 2);
        sq += __shfl_xor_sync(0xffffffffu, sq, 4);
        sq += __shfl_xor_sync(0xffffffffu, sq, 8);
        const float v = s * sqrtf(sq) / (1.f + sq);   // sn*s/((1+sn)*sqrt(sn))
        if (accum_vs) sm[OFF_VS + t] += v;
        if (outp)     outp[t] = v;
    }
    __syncthreads();
}

__device__ __forceinline__ void routing_pass(float* sm, const float* __restrict__ xb,
                                             const float* __restrict__ W,
                                             int t, int c, int g)
{
    // WV[c,o,q] = sum_p W[c,o,p,q] * vsum[o,p]; 320 (c,o) pairs over 256 threads.
    {
        int pi = t;
        #pragma unroll
        for (int rep = 0; rep < 2; ++rep, pi += NT) {
            if (pi < 320) {
                const int c2 = pi & 31;
                const int o  = pi >> 5;
                const double2* wp = reinterpret_cast<const double2*>(
                    W + (size_t)(c2 * O_ + o) * P_ * Q_);
                double wv0 = 0.0, wv1 = 0.0, wv2 = 0.0, wv3 = 0.0;
                #pragma unroll
                for (int p = 0; p < 16; ++p) {
                    const float  vs = sm[OFF_VS + o * 16 + p];
                    const double vv = dpack(vs, vs);
                    const double2 wa = wp[p * 2], wb = wp[p * 2 + 1];
                    wv0 = dfma2(wa.x, vv, wv0); wv1 = dfma2(wa.y, vv, wv1);
                    wv2 = dfma2(wb.x, vv, wv2); wv3 = dfma2(wb.y, vv, wv3);
                }
                double* dst = reinterpret_cast<double*>(sm + OFF_WV + c2 * WV_ROW + o * 8);
                dst[0] = wv0; dst[1] = wv1; dst[2] = wv2; dst[3] = wv3;
            }
        }
    }
    __syncthreads();

    // Preload this thread's WV row into registers (only LDS of the hot path).
    double wv[40];
    {
        const double2* p2 = reinterpret_cast<const double2*>(sm + OFF_WV + c * WV_ROW);
        #pragma unroll
        for (int k = 0; k < 20; ++k) { const double2 v = p2[k]; wv[2*k] = v.x; wv[2*k+1] = v.y; }
    }

    double y2[40];
    #pragma unroll
    for (int k = 0; k < 40; ++k) y2[k] = 0.0;

    // 18 hw per thread, 2 per iteration; pure register math inside.
    const double2* xp = reinterpret_cast<const double2*>(xb + (g * 18) * 8);
    #pragma unroll 3
    for (int it = 0; it < 9; ++it) {
        const double2 x0a = xp[it*4+0], x0b = xp[it*4+1];
        const double2 x1a = xp[it*4+2], x1b = xp[it*4+3];

        float bl0[10], bl1[10];
        #pragma unroll
        for (int o = 0; o < 10; ++o) {
            double a = dmul2(wv[o*4+0], x0a.x);
            a = dfma2(wv[o*4+1], x0a.y, a);
            a = dfma2(wv[o*4+2], x0b.x, a);
            a = dfma2(wv[o*4+3], x0b.y, a);
            double b = dmul2(wv[o*4+0], x1a.x);
            b = dfma2(wv[o*4+1], x1a.y, b);
            b = dfma2(wv[o*4+2], x1b.x, b);
            b = dfma2(wv[o*4+3], x1b.y, b);
            bl0[o] = dhadd(a); bl1[o] = dhadd(b);
        }
        // softmax (no max-subtract: |logit| << 88 for N(0,1) data)
        float Z0 = 0.f, Z1 = 0.f;
        #pragma unroll
        for (int o = 0; o < 10; ++o) {
            bl0[o] = __expf(bl0[o]); Z0 += bl0[o];
            bl1[o] = __expf(bl1[o]); Z1 += bl1[o];
        }
        const float rz0 = __fdividef(1.f, Z0);
        const float rz1 = __fdividef(1.f, Z1);
        #pragma unroll
        for (int o = 0; o < 10; ++o) {
            const float f0 = bl0[o] * rz0, f1 = bl1[o] * rz1;
            const double c0 = dpack(f0, f0), c1 = dpack(f1, f1);
            y2[o*4+0] = dfma2(c0, x0a.x, dfma2(c1, x1a.x, y2[o*4+0]));
            y2[o*4+1] = dfma2(c0, x0a.y, dfma2(c1, x1a.y, y2[o*4+1]));
            y2[o*4+2] = dfma2(c0, x0b.x, dfma2(c1, x1b.x, y2[o*4+2]));
            y2[o*4+3] = dfma2(c0, x0b.y, dfma2(c1, x1b.y, y2[o*4+3]));
        }
    }

    // spill per-thread y partials (82-float rows, conflict-free 8B access)
    {
        double* prow = reinterpret_cast<double*>(sm + OFF_PART + t * PART_ROW);
        #pragma unroll
        for (int k = 0; k < 40; ++k) prow[k] = y2[k];
    }
    __syncthreads();

    // reduce over the 8 hw-group warps: 1280 (c,o,qd) slots, 5 per thread
    #pragma unroll
    for (int k = 0; k < 5; ++k) {
        const int slot = t + NT * k;
        const int c2   = slot & 31;
        const int rest = slot >> 5;          // = o*4 + qd, 0..39
        double s0 = 0.0, s1 = 0.0;
        #pragma unroll
        for (int gg = 0; gg < 8; gg += 2) {
            s0 = dadd2(s0, reinterpret_cast<const double*>(
                     sm + OFF_PART + ((gg    ) * 32 + c2) * PART_ROW)[rest]);
            s1 = dadd2(s1, reinterpret_cast<const double*>(
                     sm + OFF_PART + ((gg + 1) * 32 + c2) * PART_ROW)[rest]);
        }
        reinterpret_cast<double*>(sm + OFF_Y + c2 * Y_ROW)[rest] = dadd2(s0, s1);
    }
    __syncthreads();
}

__global__ __launch_bounds__(NT, 1)
void digitcaps_kernel(const float* __restrict__ x, const float* __restrict__ W,
                      float* __restrict__ out)
{
    extern __shared__ float sm[];
    const int t = threadIdx.x;
    const int b = blockIdx.x;
    const int c = t & 31;   // lane = input channel
    const int g = t >> 5;   // warp = hw group (8 groups x 18 hw)
    const float* xb = x + ((size_t)b * C_ + c) * HW_ * Q_;

    if (t < 160) sm[OFF_VS + t] = 0.f;

    // ---- pass 0: c_ij = 0.1 exactly -> y[c,o,q] = 0.1 * sum_hw x[c,hw,q]
    {
        const int c2 = t >> 3, q = t & 7;
        const float* p = x + ((size_t)b * C_ + c2) * HW_ * Q_ + q;
        float a0 = 0.f, a1 = 0.f, a2 = 0.f, a3 = 0.f;
        #pragma unroll
        for (int hw = 0; hw < HW_; hw += 4) {
            a0 += p[(hw + 0) * 8];
            a1 += p[(hw + 1) * 8];
            a2 += p[(hw + 2) * 8];
            a3 += p[(hw + 3) * 8];
        }
        const float acc = ((a0 + a1) + (a2 + a3)) * 0.1f;
        #pragma unroll
        for (int o = 0; o < 10; ++o) sm[OFF_Y + c2 * Y_ROW + o * 8 + q] = acc;
    }
    __syncthreads();
    squash_update(sm, W, true, nullptr, t);          // vsum = v0

    // ---- pass 1: logits use v0
    routing_pass(sm, xb, W, t, c, g);
    squash_update(sm, W, true, nullptr, t);          // vsum = v0 + v1

    // ---- pass 2: logits use v0+v1; squash -> output
    routing_pass(sm, xb, W, t, c, g);
    squash_update(sm, W, false, out + (size_t)b * 160, t);
}

extern "C" void kernel_launch(void* const* d_in, const int* in_sizes, int n_in,
                              void* d_out, int out_size)
{
    (void)in_sizes; (void)n_in; (void)out_size;
    const float* x = (const float*)d_in[0];
    const float* W = (const float*)d_in[1];
    float* out = (float*)d_out;

    const int smem_bytes = SMEM_FLOATS * (int)sizeof(float);  // ~106 KB
    cudaFuncSetAttribute(digitcaps_kernel,
                         cudaFuncAttributeMaxDynamicSharedMemorySize, smem_bytes);
    digitcaps_kernel<<<128, NT, smem_bytes>>>(x, W, out);
}

// round 13
// speedup vs baseline: 1.0505x; 1.0505x over previous
#include <cuda_runtime.h>

// DigitCaps dynamic routing, fully fused, one block per batch element.
// Round 3: 256 fat threads; WV and y both register-resident in the main loop
// (zero LDS in the hot path); RF-feasible (≈220 regs x 256 thr < 64K).

#define C_   32
#define HW_  144
#define Q_   8
#define O_   10
#define P_   16
#define NT   256      // 32 c-lanes x 8 hw-group warps; 18 hw per thread

// shared memory layout (floats)
#define OFF_WV   0                       // WV per-c rows: [c*84 + o*8 + q]
#define WV_ROW   84                      // 16B-aligned rows; 20*lane conflict-free per 8-phase
#define OFF_Y    2688                    // y: [c*82 + o*8 + q]
#define Y_ROW    82                      // 18*lane distinct per 16-phase (8B ops)
#define OFF_PART 5312                    // per-thread y partials [256][82]
#define PART_ROW 82
#define OFF_VS   (OFF_PART + NT*PART_ROW)    // 26304: vsum accumulator [160]
#define SMEM_FLOATS (OFF_VS + 160)           // 26464 floats = 105856 B

// ---- packed fp32x2 helpers (double = 64-bit carrier) ----
__device__ __forceinline__ double dfma2(double a, double b, double c) {
    double d; asm("fma.rn.f32x2 %0,%1,%2,%3;" : "=d"(d) : "d"(a), "d"(b), "d"(c)); return d;
}
__device__ __forceinline__ double dmul2(double a, double b) {
    double d; asm("mul.rn.f32x2 %0,%1,%2;" : "=d"(d) : "d"(a), "d"(b)); return d;
}
__device__ __forceinline__ double dadd2(double a, double b) {
    double d; asm("add.rn.f32x2 %0,%1,%2;" : "=d"(d) : "d"(a), "d"(b)); return d;
}
__device__ __forceinline__ double dpack(float lo, float hi) {
    double d; asm("mov.b64 %0,{%1,%2};" : "=d"(d) : "f"(lo), "f"(hi)); return d;
}
__device__ __forceinline__ float dhadd(double a) {
    float lo, hi; asm("mov.b64 {%0,%1},%2;" : "=f"(lo), "=f"(hi) : "d"(a)); return lo + hi;
}

__device__ __forceinline__ double s_part(const float* __restrict__ W, const float* sm,
                                         int cc, int o, int p, double acc)
{
    const double2* wp = reinterpret_cast<const double2*>(
        W + ((size_t)(cc * O_ + o) * P_ + p) * Q_);
    const double* yp = reinterpret_cast<const double*>(sm + OFF_Y + cc * Y_ROW + o * 8);
    const double2 wa = wp[0], wb = wp[1];
    acc = dfma2(wa.x, yp[0], acc); acc = dfma2(wa.y, yp[1], acc);
    acc = dfma2(wb.x, yp[2], acc); acc = dfma2(wb.y, yp[3], acc);
    return acc;
}

// s[o,p] = sum_{c,q} W[c,o,p,q]*y[c,o,q]  -> squash -> vsum/out. Single stage.
__device__ __forceinline__ void squash_update(float* sm, const float* __restrict__ W,
                                              bool accum_vs, float* __restrict__ outp, int t)
{
    if (t < 160) {
        const int o = t >> 4, p = t & 15;
        double a0 = 0.0, a1 = 0.0, a2 = 0.0, a3 = 0.0;
        #pragma unroll
        for (int ci = 0; ci < 8; ++ci) {
            a0 = s_part(W, sm, ci,      o, p, a0);
            a1 = s_part(W, sm, ci + 8,  o, p, a1);
            a2 = s_part(W, sm, ci + 16, o, p, a2);
            a3 = s_part(W, sm, ci + 24, o, p, a3);
        }
        const float s = dhadd(dadd2(dadd2(a0, a1), dadd2(a2, a3)));
        float sq = s * s;
        sq += __shfl_xor_sync(0xffffffffu, sq, 1);
        sq += __shfl_xor_sync(0xffffffffu, sq, 2);
        sq += __shfl_xor_sync(0xffffffffu, sq, 4);
        sq += __shfl_xor_sync(0xffffffffu, sq, 8);
        const float v = s * sqrtf(sq) / (1.f + sq);   // sn*s/((1+sn)*sqrt(sn))
        if (accum_vs) sm[OFF_VS + t] += v;
        if (outp)     outp[t] = v;
    }
    __syncthreads();
}

__device__ __forceinline__ void routing_pass(float* sm, const float* __restrict__ xb,
                                             const float* __restrict__ W,
                                             int t, int c, int g)
{
    // WV[c,o,q] = sum_p W[c,o,p,q] * vsum[o,p]; 320 (c,o) pairs over 256 threads.
    {
        int pi = t;
        #pragma unroll
        for (int rep = 0; rep < 2; ++rep, pi += NT) {
            if (pi < 320) {
                const int c2 = pi & 31;
                const int o  = pi >> 5;
                const double2* wp = reinterpret_cast<const double2*>(
                    W + (size_t)(c2 * O_ + o) * P_ * Q_);
                double wv0 = 0.0, wv1 = 0.0, wv2 = 0.0, wv3 = 0.0;
                #pragma unroll
                for (int p = 0; p < 16; ++p) {
                    const float  vs = sm[OFF_VS + o * 16 + p];
                    const double vv = dpack(vs, vs);
                    const double2 wa = wp[p * 2], wb = wp[p * 2 + 1];
                    wv0 = dfma2(wa.x, vv, wv0); wv1 = dfma2(wa.y, vv, wv1);
                    wv2 = dfma2(wb.x, vv, wv2); wv3 = dfma2(wb.y, vv, wv3);
                }
                double* dst = reinterpret_cast<double*>(sm + OFF_WV + c2 * WV_ROW + o * 8);
                dst[0] = wv0; dst[1] = wv1; dst[2] = wv2; dst[3] = wv3;
            }
        }
    }
    __syncthreads();

    // Preload this thread's WV row into registers (only LDS of the hot path).
    double wv[40];
    {
        const double2* p2 = reinterpret_cast<const double2*>(sm + OFF_WV + c * WV_ROW);
        #pragma unroll
        for (int k = 0; k < 20; ++k) { const double2 v = p2[k]; wv[2*k] = v.x; wv[2*k+1] = v.y; }
    }

    double y2[40];
    #pragma unroll
    for (int k = 0; k < 40; ++k) y2[k] = 0.0;

    // 18 hw per thread, 2 per iteration; pure register math inside.
    const double2* xp = reinterpret_cast<const double2*>(xb + (g * 18) * 8);
    #pragma unroll 3
    for (int it = 0; it < 9; ++it) {
        const double2 x0a = xp[it*4+0], x0b = xp[it*4+1];
        const double2 x1a = xp[it*4+2], x1b = xp[it*4+3];

        float bl0[10], bl1[10];
        #pragma unroll
        for (int o = 0; o < 10; ++o) {
            double a = dmul2(wv[o*4+0], x0a.x);
            a = dfma2(wv[o*4+1], x0a.y, a);
            a = dfma2(wv[o*4+2], x0b.x, a);
            a = dfma2(wv[o*4+3], x0b.y, a);
            double b = dmul2(wv[o*4+0], x1a.x);
            b = dfma2(wv[o*4+1], x1a.y, b);
            b = dfma2(wv[o*4+2], x1b.x, b);
            b = dfma2(wv[o*4+3], x1b.y, b);
            bl0[o] = dhadd(a); bl1[o] = dhadd(b);
        }
        // softmax (no max-subtract: |logit| << 88 for N(0,1) data)
        float Z0 = 0.f, Z1 = 0.f;
        #pragma unroll
        for (int o = 0; o < 10; ++o) {
            bl0[o] = __expf(bl0[o]); Z0 += bl0[o];
            bl1[o] = __expf(bl1[o]); Z1 += bl1[o];
        }
        const float rz0 = __fdividef(1.f, Z0);
        const float rz1 = __fdividef(1.f, Z1);
        #pragma unroll
        for (int o = 0; o < 10; ++o) {
            const float f0 = bl0[o] * rz0, f1 = bl1[o] * rz1;
            const double c0 = dpack(f0, f0), c1 = dpack(f1, f1);
            y2[o*4+0] = dfma2(c0, x0a.x, dfma2(c1, x1a.x, y2[o*4+0]));
            y2[o*4+1] = dfma2(c0, x0a.y, dfma2(c1, x1a.y, y2[o*4+1]));
            y2[o*4+2] = dfma2(c0, x0b.x, dfma2(c1, x1b.x, y2[o*4+2]));
            y2[o*4+3] = dfma2(c0, x0b.y, dfma2(c1, x1b.y, y2[o*4+3]));
        }
    }

    // spill per-thread y partials (82-float rows, conflict-free 8B access)
    {
        double* prow = reinterpret_cast<double*>(sm + OFF_PART + t * PART_ROW);
        #pragma unroll
        for (int k = 0; k < 40; ++k) prow[k] = y2[k];
    }
    __syncthreads();

    // reduce over the 8 hw-group warps: 1280 (c,o,qd) slots, 5 per thread
    #pragma unroll
    for (int k = 0; k < 5; ++k) {
        const int slot = t + NT * k;
        const int c2   = slot & 31;
        const int rest = slot >> 5;          // = o*4 + qd, 0..39
        double s0 = 0.0, s1 = 0.0;
        #pragma unroll
        for (int gg = 0; gg < 8; gg += 2) {
            s0 = dadd2(s0, reinterpret_cast<const double*>(
                     sm + OFF_PART + ((gg    ) * 32 + c2) * PART_ROW)[rest]);
            s1 = dadd2(s1, reinterpret_cast<const double*>(
                     sm + OFF_PART + ((gg + 1) * 32 + c2) * PART_ROW)[rest]);
        }
        reinterpret_cast<double*>(sm + OFF_Y + c2 * Y_ROW)[rest] = dadd2(s0, s1);
    }
    __syncthreads();
}

__global__ __launch_bounds__(NT, 1)
void digitcaps_kernel(const float* __restrict__ x, const float* __restrict__ W,
                      float* __restrict__ out)
{
    extern __shared__ float sm[];
    const int t = threadIdx.x;
    const int b = blockIdx.x;
    const int c = t & 31;   // lane = input channel
    const int g = t >> 5;   // warp = hw group (8 groups x 18 hw)
    const float* xb = x + ((size_t)b * C_ + c) * HW_ * Q_;

    if (t < 160) sm[OFF_VS + t] = 0.f;

    // ---- pass 0: c_ij = 0.1 exactly -> y[c,o,q] = 0.1 * sum_hw x[c,hw,q]
    {
        const int c2 = t >> 3, q = t & 7;
        const float* p = x + ((size_t)b * C_ + c2) * HW_ * Q_ + q;
        float a0 = 0.f, a1 = 0.f, a2 = 0.f, a3 = 0.f;
        #pragma unroll
        for (int hw = 0; hw < HW_; hw += 4) {
            a0 += p[(hw + 0) * 8];
            a1 += p[(hw + 1) * 8];
            a2 += p[(hw + 2) * 8];
            a3 += p[(hw + 3) * 8];
        }
        const float acc = ((a0 + a1) + (a2 + a3)) * 0.1f;
        #pragma unroll
        for (int o = 0; o < 10; ++o) sm[OFF_Y + c2 * Y_ROW + o * 8 + q] = acc;
    }
    __syncthreads();
    squash_update(sm, W, true, nullptr, t);          // vsum = v0

    // ---- pass 1: logits use v0
    routing_pass(sm, xb, W, t, c, g);
    squash_update(sm, W, true, nullptr, t);          // vsum = v0 + v1

    // ---- pass 2: logits use v0+v1; squash -> output
    routing_pass(sm, xb, W, t, c, g);
    squash_update(sm, W, false, out + (size_t)b * 160, t);
}

extern "C" void kernel_launch(void* const* d_in, const int* in_sizes, int n_in,
                              void* d_out, int out_size)
{
    (void)in_sizes; (void)n_in; (void)out_size;
    const float* x = (const float*)d_in[0];
    const float* W = (const float*)d_in[1];
    float* out = (float*)d_out;

    const int smem_bytes = SMEM_FLOATS * (int)sizeof(float);  // ~106 KB
    cudaFuncSetAttribute(digitcaps_kernel,
                         cudaFuncAttributeMaxDynamicSharedMemorySize, smem_bytes);
    digitcaps_kernel<<<128, NT, smem_bytes>>>(x, W, out);
}